// round 10
// baseline (speedup 1.0000x reference)
#include <cuda_runtime.h>

#define DX 16
#define DU 16
#define DA 32
#define NSEQ 256
#define NSTEP 1024

// Precomputed constants (setup kernel): Q = C^T R^-1 C, CtR = C^T R^-1, W = exp(Wlog)
__device__ float g_Q[DX * DX];
__device__ float g_CtR[DX * DA];
__device__ float g_W[DX];

__global__ void ldm_setup(const float* __restrict__ C,
                          const float* __restrict__ Wlog,
                          const float* __restrict__ Rlog)
{
    int t = threadIdx.x;  // 256 threads
    if (t < DX) g_W[t] = expf(Wlog[t]);
    for (int e = t; e < DX * DA; e += blockDim.x) {
        int i = e / DA, j = e % DA;
        g_CtR[e] = C[j * DX + i] * expf(-Rlog[j]);
    }
    if (t < DX * DX) {
        int i = t / DX, l = t % DX;
        float acc = 0.f;
        for (int j = 0; j < DA; j++)
            acc += C[j * DX + i] * expf(-Rlog[j]) * C[j * DX + l];
        g_Q[t] = acc;
    }
}

__global__ __launch_bounds__(128) void ldm_forward(
    const float* __restrict__ a, const float* __restrict__ u,
    const float* __restrict__ mask,
    const float* __restrict__ A, const float* __restrict__ B,
    const float* __restrict__ C,
    const float* __restrict__ mu0, const float* __restrict__ Lam0,
    float* __restrict__ out)
{
    __shared__ float sA[DX][17];
    __shared__ float sB[DX][17];
    __shared__ float sQ[DX][17];
    __shared__ float sW[DX];
    __shared__ float sCt[DX][DA];       // sCt[k][j] = C[j][k]
    __shared__ float sCtR[DX][DA + 1];  // padded: stride-33 kills bank conflicts
    __shared__ float Lp[DX][17];        // Lambda_pred (carry)
    __shared__ float Lt[DX][17];        // Lambda_t
    __shared__ float Ut[DX][17];        // (Lt * A^T)^T
    __shared__ float Gm[DX][17];        // G = I + Lp*Q
    __shared__ float mu_p[DX], mu_ts[DX], r_s[DA], v_s[DX];

    const int tid = threadIdx.x;
    const int b   = blockIdx.x;
    const int i   = tid >> 3;      // output row   (0..15)
    const int j0  = tid & 7;       // output col A (0..7)
    const int j1  = j0 + 8;        // output col B (8..15)

    // ---- load constants / initial state into smem ----
    for (int e = tid; e < DX * DX; e += 128) {
        int r = e >> 4, c = e & 15;
        sA[r][c] = A[e];
        sB[r][c] = B[e];
        sQ[r][c] = g_Q[e];
        Lp[r][c] = Lam0[e];
    }
    for (int e = tid; e < DX * DA; e += 128) {
        int k = e >> 5, j = e & 31;
        sCt[k][j]  = C[j * DX + k];
        sCtR[k][j] = g_CtR[k * DA + j];
    }
    if (tid < DX) { sW[tid] = g_W[tid]; mu_p[tid] = mu0[tid]; }
    __syncthreads();

    const float* a_b = a    + (size_t)b * NSTEP * DA;
    const float* u_b = u    + (size_t)b * NSTEP * DU;
    const float* m_b = mask + (size_t)b * NSTEP;

    float* o_mp = out;                                        // mu_pred_all  [T,B,16]
    float* o_mt = out + (size_t)NSTEP * NSEQ * DX;            // mu_t_all     [T,B,16]
    float* o_Lp = out + (size_t)2 * NSTEP * NSEQ * DX;        // Lam_pred_all [T,B,16,16]
    float* o_Lt = o_Lp + (size_t)NSTEP * NSEQ * DX * DX;      // Lam_t_all    [T,B,16,16]

    #pragma unroll 1
    for (int t = 0; t < NSTEP; t++) {
        // ---- deferred stores of step t-1's post-update prediction (hides STG latency) ----
        if (t > 0) {
            size_t baseL = ((size_t)(t - 1) * NSEQ + b) * (DX * DX);
            o_Lp[baseL + tid]       = Lp[tid >> 4][tid & 15];
            o_Lp[baseL + 128 + tid] = Lp[8 + (tid >> 4)][tid & 15];
            if (tid < DX)
                o_mp[((size_t)(t - 1) * NSEQ + b) * DX + tid] = mu_p[tid];
        }

        const float m = m_b[t];  // same address for all threads -> uniform

        // ---- P1: G = I + Lp*Q  (2 elements per thread) ----
        {
            float g0 = (i == j0) ? 1.f : 0.f;
            float g1 = (i == j1) ? 1.f : 0.f;
            #pragma unroll
            for (int k = 0; k < DX; k++) {
                float lp = Lp[i][k];
                g0 += lp * sQ[k][j0];
                g1 += lp * sQ[k][j1];
            }
            Gm[i][j0] = g0;
            Gm[i][j1] = g1;
        }
        // r = m*a_t - C*mu_pred  (threads 0..31)
        if (tid < DA) {
            float racc = m * a_b[(size_t)t * DA + tid];
            #pragma unroll
            for (int k = 0; k < DX; k++)
                racc -= sCt[k][tid] * mu_p[k];
            r_s[tid] = racc;
        }
        __syncthreads();  // B1

        // ---- P2: warp0 solves (I + Lp*Q) * Lt = Lp  in registers; warp1 computes v ----
        if (m > 0.5f) {
            if (tid < 32) {
                // lane j<16 owns column j of G; lane j>=16 owns column j-16 of RHS (Lp)
                float col[DX];
                #pragma unroll
                for (int q = 0; q < DX; q++)
                    col[q] = (tid < 16) ? Gm[q][tid] : Lp[q][tid - 16];
                #pragma unroll
                for (int k = 0; k < DX; k++) {
                    float pivot = __shfl_sync(0xffffffffu, col[k], k);  // G[k][k]
                    float pinv  = 1.0f / pivot;
                    float pr    = col[k] * pinv;                        // scaled pivot-row elem
                    #pragma unroll
                    for (int q = 0; q < DX; q++) {
                        float f = __shfl_sync(0xffffffffu, col[q], k);  // G[q][k]
                        col[q] = (q == k) ? pr : col[q] - f * pr;
                    }
                }
                if (tid >= 16) {
                    #pragma unroll
                    for (int q = 0; q < DX; q++)
                        Lt[q][tid - 16] = col[q];
                }
            } else if (tid < 48) {
                // v = (C^T R^-1) * r
                int ii = tid - 32;
                float acc = 0.f;
                #pragma unroll
                for (int j = 0; j < DA; j++)
                    acc += sCtR[ii][j] * r_s[j];
                v_s[ii] = acc;
            }
        } else {
            // mask == 0: no measurement update
            Lt[i][j0] = Lp[i][j0];
            Lt[i][j1] = Lp[i][j1];
            if (tid < DX) v_s[tid] = 0.f;
        }
        __syncthreads();  // B2

        // ---- P3: Ut[l][q] = (Lt * A^T)[q][l]; mu_t; store Lambda_t output ----
        {
            float u0 = 0.f, u1 = 0.f;
            #pragma unroll
            for (int k = 0; k < DX; k++) {
                float lt = Lt[i][k];
                u0 += lt * sA[j0][k];
                u1 += lt * sA[j1][k];
            }
            Ut[j0][i] = u0;
            Ut[j1][i] = u1;
        }
        if (tid < DX) {
            // mu_t = mu_pred + m * Lt * v   (K*r == Lt * C^T R^-1 * r)
            float acc = 0.f;
            #pragma unroll
            for (int j = 0; j < DX; j++)
                acc += Lt[tid][j] * v_s[j];
            mu_ts[tid] = mu_p[tid] + m * acc;
        }
        {
            size_t baseL = ((size_t)t * NSEQ + b) * (DX * DX);
            o_Lt[baseL + tid]       = Lt[tid >> 4][tid & 15];
            o_Lt[baseL + 128 + tid] = Lt[8 + (tid >> 4)][tid & 15];
        }
        __syncthreads();  // B3

        // ---- P4: Lp_new = A*(Lt*A^T) + W ; mu_pred_new = A*mu_t + B*u_t ----
        {
            float p0 = (i == j0) ? sW[i] : 0.f;
            float p1 = (i == j1) ? sW[i] : 0.f;
            #pragma unroll
            for (int k = 0; k < DX; k++) {
                float av = sA[i][k];
                p0 += av * Ut[j0][k];
                p1 += av * Ut[j1][k];
            }
            Lp[i][j0] = p0;
            Lp[i][j1] = p1;
        }
        if (tid < DX) {
            float acc = 0.f;
            #pragma unroll
            for (int k = 0; k < DX; k++)
                acc += sA[tid][k] * mu_ts[k];
            if (t < NSTEP - 1) {  // reference zeroes u at the final step
                #pragma unroll
                for (int k = 0; k < DU; k++)
                    acc += sB[tid][k] * u_b[(size_t)t * DU + k];
            }
            o_mt[((size_t)t * NSEQ + b) * DX + tid] = mu_ts[tid];
            mu_p[tid] = acc;
        }
        __syncthreads();  // B4
    }

    // ---- final deferred stores (t = NSTEP-1) ----
    {
        size_t baseL = ((size_t)(NSTEP - 1) * NSEQ + b) * (DX * DX);
        o_Lp[baseL + tid]       = Lp[tid >> 4][tid & 15];
        o_Lp[baseL + 128 + tid] = Lp[8 + (tid >> 4)][tid & 15];
        if (tid < DX)
            o_mp[((size_t)(NSTEP - 1) * NSEQ + b) * DX + tid] = mu_p[tid];
    }
}

extern "C" void kernel_launch(void* const* d_in, const int* in_sizes, int n_in,
                              void* d_out, int out_size)
{
    const float* a    = (const float*)d_in[0];
    const float* u    = (const float*)d_in[1];
    const float* mask = (const float*)d_in[2];
    const float* A    = (const float*)d_in[3];
    const float* B    = (const float*)d_in[4];
    const float* C    = (const float*)d_in[5];
    const float* mu0  = (const float*)d_in[6];
    const float* L0   = (const float*)d_in[7];
    const float* Wlog = (const float*)d_in[8];
    const float* Rlog = (const float*)d_in[9];
    (void)in_sizes; (void)n_in; (void)out_size;

    ldm_setup<<<1, 256>>>(C, Wlog, Rlog);
    ldm_forward<<<NSEQ, 128>>>(a, u, mask, A, B, C, mu0, L0, (float*)d_out);
}